// round 10
// baseline (speedup 1.0000x reference)
#include <cuda_runtime.h>
#include <cuda_bf16.h>
#include <math.h>
#include <stdint.h>

typedef uint32_t u32;

#define NBLK 128
#define NTHR 512
#define BB   32
#define CC   1024
#define C2   2048
#define TT   1024
#define WS   2056   // weight row stride (bf16 elems): conflict-free LDSM

// SMEM: weights (bf16) + sRed (float)
#define OFF_WAHI  0
#define OFF_WALO  (16*WS)
#define OFF_WBHI  (32*WS)
#define OFF_WBLO  (40*WS)
#define OFF_END   (48*WS)
#define SRED_FLOATS 2560
#define SMEM_BYTES (OFF_END*2 + SRED_FLOATS*4)   // 207,616 B

__device__ __nv_bfloat16 g_x_hi[33554432];
__device__ __nv_bfloat16 g_x_lo[33554432];
__device__ __nv_bfloat16 g_h_hi[BB*CC];
__device__ __nv_bfloat16 g_h_lo[BB*CC];
__device__ __nv_bfloat16 g_y_hi[BB*C2];
__device__ __nv_bfloat16 g_y_lo[BB*C2];
__device__ float g_y2[BB*CC];
__device__ unsigned g_cnt;
__device__ volatile unsigned g_gen;

__device__ __forceinline__ float geluf(float u) {
    return 0.5f * u * (1.0f + erff(u * 0.70710678118654752440f));
}

__device__ __forceinline__ void gbar() {
    __syncthreads();
    if (threadIdx.x == 0) {
        __threadfence();
        unsigned gen = g_gen;
        if (atomicAdd(&g_cnt, 1u) == NBLK - 1) {
            atomicExch(&g_cnt, 0u);
            __threadfence();
            g_gen = gen + 1u;
        } else {
            while (g_gen == gen) {}
        }
        __threadfence();
    }
    __syncthreads();
}

__device__ __forceinline__ void ldsm4(u32 (&r)[4], u32 addr) {
    asm volatile("ldmatrix.sync.aligned.m8n8.x4.shared.b16 {%0,%1,%2,%3}, [%4];"
        : "=r"(r[0]), "=r"(r[1]), "=r"(r[2]), "=r"(r[3]) : "r"(addr));
}
__device__ __forceinline__ void ldsm2(u32 (&r)[2], u32 addr) {
    asm volatile("ldmatrix.sync.aligned.m8n8.x2.shared.b16 {%0,%1}, [%2];"
        : "=r"(r[0]), "=r"(r[1]) : "r"(addr));
}
__device__ __forceinline__ void mma16816(float (&c)[4], const u32 (&a)[4], const u32 (&b)[2]) {
    asm volatile("mma.sync.aligned.m16n8k16.row.col.f32.bf16.bf16.f32 "
        "{%0,%1,%2,%3}, {%4,%5,%6,%7}, {%8,%9}, {%0,%1,%2,%3};"
        : "+f"(c[0]), "+f"(c[1]), "+f"(c[2]), "+f"(c[3])
        : "r"(a[0]), "r"(a[1]), "r"(a[2]), "r"(a[3]), "r"(b[0]), "r"(b[1]));
}
__device__ __forceinline__ u32 ldcg32(const __nv_bfloat16* p) {
    return __ldcg((const unsigned int*)p);
}

__device__ __forceinline__ void split2(float v, __nv_bfloat16& h, __nv_bfloat16& l) {
    h = __float2bfloat16_rn(v);
    l = __float2bfloat16_rn(v - __bfloat162float(h));
}

__global__ void __launch_bounds__(NTHR, 1)
rnn_kernel(const float* __restrict__ x,   const float* __restrict__ Wa,
           const float* __restrict__ ba,  const float* __restrict__ Wb,
           const float* __restrict__ bbv, const float* __restrict__ gamma,
           const float* __restrict__ beta, float* __restrict__ out)
{
    extern __shared__ __nv_bfloat16 smb[];
    __nv_bfloat16* sWaHi = smb + OFF_WAHI;
    __nv_bfloat16* sWaLo = smb + OFF_WALO;
    __nv_bfloat16* sWbHi = smb + OFF_WBHI;
    __nv_bfloat16* sWbLo = smb + OFF_WBLO;
    float* sRed = (float*)(smb + OFF_END);

    const int tid = threadIdx.x;
    const int cta = blockIdx.x;
    const int lane = tid & 31, wid = tid >> 5;

    // ---- one-time: weights -> smem bf16 hi/lo planes ----
    for (int idx = tid; idx < 16*C2; idx += NTHR) {
        int r = idx >> 11, k = idx & (C2-1);
        float v = Wa[(size_t)(cta*16 + r)*C2 + k];
        split2(v, sWaHi[r*WS + k], sWaLo[r*WS + k]);
    }
    for (int idx = tid; idx < 8*C2; idx += NTHR) {
        int r = idx >> 11, k = idx & (C2-1);
        float v = Wb[(size_t)(cta*8 + r)*C2 + k];
        split2(v, sWbHi[r*WS + k], sWbLo[r*WS + k]);
    }
    // ---- one-time: x -> bf16 hi/lo global planes ----
    {
        int g = cta*NTHR + tid;
        const float4* x4 = (const float4*)x;
        uint2* xh = (uint2*)g_x_hi;
        uint2* xl = (uint2*)g_x_lo;
        for (int i = 0; i < 128; ++i) {
            int idx = g + (i << 16);
            float4 v = x4[idx];
            __nv_bfloat16 h0,h1,h2,h3,l0,l1,l2,l3;
            split2(v.x,h0,l0); split2(v.y,h1,l1); split2(v.z,h2,l2); split2(v.w,h3,l3);
            __nv_bfloat162 ph0 = {h0,h1}, ph1 = {h2,h3}, pl0 = {l0,l1}, pl1 = {l2,l3};
            uint2 uh, ul;
            uh.x = *(u32*)&ph0; uh.y = *(u32*)&ph1;
            ul.x = *(u32*)&pl0; ul.y = *(u32*)&pl1;
            xh[idx] = uh; xl[idx] = ul;
        }
    }
    {
        int idx = cta*NTHR + tid;
        if (idx < BB*CC) {
            g_h_hi[idx] = __float2bfloat16_rn(0.f);
            g_h_lo[idx] = __float2bfloat16_rn(0.f);
        }
    }
    gbar();

    // ---- warp roles ----
    // Phase A: D[16j x 32b]: nt = wid>>2 (8-b tile), kspA = wid&3 (4-way k-split of 2048)
    const int kspA = wid & 3, nt = wid >> 2;
    // Phase B: D[32b x 8j]: mtB = wid&1 (16-b tile), kspB = wid>>1 (8-way k-split)
    const int mtB = wid & 1, kspB = wid >> 1;
    const int myB = cta >> 2, myQ = cta & 3;

    // weight ldmatrix bases
    const u32 smemBase = (u32)__cvta_generic_to_shared(smb);
    const int aRow = lane & 15, aKh = (lane >> 4) * 8;
    const int bRow = lane & 7,  bKh = ((lane >> 3) & 1) * 8;
    const u32 waHi = smemBase + OFF_WAHI*2 + (aRow*WS + aKh)*2 + kspA*512*2;
    const u32 waLo = smemBase + OFF_WALO*2 + (aRow*WS + aKh)*2 + kspA*512*2;
    const u32 wbHi = smemBase + OFF_WBHI*2 + (bRow*WS + bKh)*2 + kspB*256*2;
    const u32 wbLo = smemBase + OFF_WBLO*2 + (bRow*WS + bKh)*2 + kspB*256*2;

    // ---- direct-LDG fragment pointers ----
    const int kLane = (lane & 3) * 2;
    // Phase A B-frag: act row = nt*8 + (lane>>2), k = kspA*512 + ks*16 + kLane (+8 for b1)
    const int bRowA = nt*8 + (lane >> 2);
    const __nv_bfloat16* pHh = g_h_hi + (size_t)bRowA*CC + kspA*512 + kLane;   // valid kspA<2
    const __nv_bfloat16* pHl = g_h_lo + (size_t)bRowA*CC + kspA*512 + kLane;
    const size_t xbase = (size_t)bRowA*TT*CC + (size_t)(kspA-2)*512 + kLane;   // valid kspA>=2
    // Phase B A-frag: rows r0B, r0B+8; k = kspB*256 + ks*16 + kLane (+8 for a2/a3)
    const int r0B = mtB*16 + (lane >> 2);
    const __nv_bfloat16* pY0h = g_y_hi + (size_t)r0B*C2 + kspB*256 + kLane;
    const __nv_bfloat16* pY1h = pY0h + 8*C2;
    const __nv_bfloat16* pY0l = g_y_lo + (size_t)r0B*C2 + kspB*256 + kLane;
    const __nv_bfloat16* pY1l = pY0l + 8*C2;

    for (int t = 0; t < TT; ++t) {
        // ================= Phase A: y = gelu([h,x_t] @ Wa^T + ba) =================
        float c0[4] = {0,0,0,0}, c1[4] = {0,0,0,0}, c2[4] = {0,0,0,0};
        {
            const __nv_bfloat16 *ph, *pl;
            if (kspA < 2) { ph = pHh; pl = pHl; }
            else { ph = g_x_hi + xbase + (size_t)t*CC; pl = g_x_lo + xbase + (size_t)t*CC; }
            #pragma unroll 4
            for (int ks = 0; ks < 32; ++ks) {
                u32 Bh[2], Bl[2], Ah[4], Al[4];
                Bh[0] = ldcg32(ph + ks*16);
                Bh[1] = ldcg32(ph + ks*16 + 8);
                Bl[0] = ldcg32(pl + ks*16);
                Bl[1] = ldcg32(pl + ks*16 + 8);
                ldsm4(Ah, waHi + ks*32);
                ldsm4(Al, waLo + ks*32);
                mma16816(c0, Ah, Bh);
                mma16816(c1, Ah, Bl);
                mma16816(c2, Al, Bh);
            }
        }
        {   // partials -> sRed[kspA][16j][32b] (row stride 34)
            const int r0 = lane >> 2, cb = nt*8 + 2*(lane & 3);
            float2 v0 = make_float2(c0[0]+c1[0]+c2[0], c0[1]+c1[1]+c2[1]);
            float2 v1 = make_float2(c0[2]+c1[2]+c2[2], c0[3]+c1[3]+c2[3]);
            *(float2*)(sRed + (kspA*16 + r0    )*34 + cb) = v0;
            *(float2*)(sRed + (kspA*16 + r0 + 8)*34 + cb) = v1;
            __syncthreads();
            const int b = tid >> 4, j = tid & 15;
            float v = sRed[j*34 + b] + sRed[(16 + j)*34 + b]
                    + sRed[(32 + j)*34 + b] + sRed[(48 + j)*34 + b];
            const int jg = cta*16 + j;
            float y = geluf(v + __ldg(ba + jg));
            __nv_bfloat16 hh, ll;
            split2(y, hh, ll);
            g_y_hi[(size_t)b*C2 + jg] = hh;
            g_y_lo[(size_t)b*C2 + jg] = ll;
        }
        gbar();

        // ================= Phase B: y2 = y @ Wb^T + bb =================
        float d0[4] = {0,0,0,0}, d1[4] = {0,0,0,0}, d2[4] = {0,0,0,0};
        {
            #pragma unroll 4
            for (int ks = 0; ks < 16; ++ks) {
                u32 Ah[4], Al[4], Bh[2], Bl[2];
                Ah[0] = ldcg32(pY0h + ks*16);
                Ah[1] = ldcg32(pY1h + ks*16);
                Ah[2] = ldcg32(pY0h + ks*16 + 8);
                Ah[3] = ldcg32(pY1h + ks*16 + 8);
                Al[0] = ldcg32(pY0l + ks*16);
                Al[1] = ldcg32(pY1l + ks*16);
                Al[2] = ldcg32(pY0l + ks*16 + 8);
                Al[3] = ldcg32(pY1l + ks*16 + 8);
                ldsm2(Bh, wbHi + ks*32);
                ldsm2(Bl, wbLo + ks*32);
                mma16816(d0, Ah, Bh);
                mma16816(d1, Ah, Bl);
                mma16816(d2, Al, Bh);
            }
        }
        {   // partials -> sRed[kspB][32b][8j] (row stride 10)
            const int r0 = mtB*16 + (lane >> 2), cb = 2*(lane & 3);
            float2 v0 = make_float2(d0[0]+d1[0]+d2[0], d0[1]+d1[1]+d2[1]);
            float2 v1 = make_float2(d0[2]+d1[2]+d2[2], d0[3]+d1[3]+d2[3]);
            *(float2*)(sRed + (kspB*32 + r0    )*10 + cb) = v0;
            *(float2*)(sRed + (kspB*32 + r0 + 8)*10 + cb) = v1;
            __syncthreads();
            if (tid < 256) {
                const int b = tid >> 3, j = tid & 7;
                float v = 0.f;
                #pragma unroll
                for (int p = 0; p < 8; ++p) v += sRed[(p*32 + b)*10 + j];
                const int jg = cta*8 + j;
                v += __ldg(bbv + jg);
                __stcg(&g_y2[(size_t)b*CC + jg], v);
            }
        }
        gbar();

        // ================= Phase C: h = LN(y2)+y2 =================
        {
            float s = 0.f, sq = 0.f;
            #pragma unroll
            for (int i = tid; i < CC; i += NTHR) {
                float v = __ldcg(g_y2 + (size_t)myB*CC + i);
                s += v; sq += v*v;
            }
            #pragma unroll
            for (int o = 16; o; o >>= 1) {
                s  += __shfl_xor_sync(0xffffffffu, s,  o);
                sq += __shfl_xor_sync(0xffffffffu, sq, o);
            }
            if (lane == 0) { sRed[wid] = s; sRed[16 + wid] = sq; }
            __syncthreads();
            if (tid < 256) {
                float S = 0.f, Q = 0.f;
                #pragma unroll
                for (int w = 0; w < 16; ++w) { S += sRed[w]; Q += sRed[16 + w]; }
                float mu  = S * (1.0f / CC);
                float var = Q * (1.0f / CC) - mu * mu;
                float r   = rsqrtf(var + 1e-5f);
                int col = myQ * 256 + tid;
                float v  = __ldcg(g_y2 + (size_t)myB*CC + col);
                float hn = (v - mu) * r * __ldg(gamma + col) + __ldg(beta + col) + v;
                out[(size_t)myB*TT*CC + (size_t)t*CC + col] = hn;
                __nv_bfloat16 hh, ll;
                split2(hn, hh, ll);
                g_h_hi[(size_t)myB*CC + col] = hh;
                g_h_lo[(size_t)myB*CC + col] = ll;
            }
        }
        gbar();
    }
}

extern "C" void kernel_launch(void* const* d_in, const int* in_sizes, int n_in,
                              void* d_out, int out_size) {
    const float* x     = (const float*)d_in[0];
    const float* Wa    = (const float*)d_in[1];
    const float* ba    = (const float*)d_in[2];
    const float* Wb    = (const float*)d_in[3];
    const float* bbv   = (const float*)d_in[4];
    const float* gamma = (const float*)d_in[5];
    const float* beta  = (const float*)d_in[6];
    float* out = (float*)d_out;

    cudaFuncSetAttribute(rnn_kernel, cudaFuncAttributeMaxDynamicSharedMemorySize, SMEM_BYTES);
    rnn_kernel<<<NBLK, NTHR, SMEM_BYTES>>>(x, Wa, ba, Wb, bbv, gamma, beta, out);
}

// round 11
// speedup vs baseline: 1.6923x; 1.6923x over previous
#include <cuda_runtime.h>
#include <cuda_bf16.h>
#include <math.h>
#include <stdint.h>

typedef uint32_t u32;

#define NBLK 128
#define NTHR 512
#define BB   32
#define CC   1024
#define C2   2048
#define TT   1024
#define WS   2056   // weight row stride (bf16 elems): conflict-free LDSM
#define AS   136    // act row stride (bf16 elems): conflict-free LDSM (272B)

// SMEM (bf16-elem offsets): weights, then 2 double-buffered act chunk buffers
#define OFF_WAHI  0
#define OFF_WALO  (16*WS)
#define OFF_WBHI  (32*WS)
#define OFF_WBLO  (40*WS)
#define OFF_BUF   (48*WS)
#define PLANE     (32*AS)              // 4352 elems per plane
#define SMEM_BYTES ((OFF_BUF + 4*PLANE)*2)   // 232,192 B

__device__ __nv_bfloat16 g_x_hi[33554432];
__device__ __nv_bfloat16 g_x_lo[33554432];
__device__ __nv_bfloat16 g_h_hi[BB*CC];
__device__ __nv_bfloat16 g_h_lo[BB*CC];
__device__ __nv_bfloat16 g_y_hi[BB*C2];
__device__ __nv_bfloat16 g_y_lo[BB*C2];
__device__ float g_y2[BB*CC];
__device__ unsigned g_cnt;
__device__ volatile unsigned g_gen;

__device__ __forceinline__ float geluf(float u) {
    return 0.5f * u * (1.0f + erff(u * 0.70710678118654752440f));
}

__device__ __forceinline__ void gbar() {
    __syncthreads();
    if (threadIdx.x == 0) {
        __threadfence();
        unsigned gen = g_gen;
        if (atomicAdd(&g_cnt, 1u) == NBLK - 1) {
            atomicExch(&g_cnt, 0u);
            __threadfence();
            g_gen = gen + 1u;
        } else {
            while (g_gen == gen) {}
        }
        __threadfence();
    }
    __syncthreads();
}

__device__ __forceinline__ void ldsm4(u32 (&r)[4], u32 addr) {
    asm volatile("ldmatrix.sync.aligned.m8n8.x4.shared.b16 {%0,%1,%2,%3}, [%4];"
        : "=r"(r[0]), "=r"(r[1]), "=r"(r[2]), "=r"(r[3]) : "r"(addr));
}
__device__ __forceinline__ void ldsm2(u32 (&r)[2], u32 addr) {
    asm volatile("ldmatrix.sync.aligned.m8n8.x2.shared.b16 {%0,%1}, [%2];"
        : "=r"(r[0]), "=r"(r[1]) : "r"(addr));
}
__device__ __forceinline__ void mma16816(float (&c)[4], const u32 (&a)[4], const u32 (&b)[2]) {
    asm volatile("mma.sync.aligned.m16n8k16.row.col.f32.bf16.bf16.f32 "
        "{%0,%1,%2,%3}, {%4,%5,%6,%7}, {%8,%9}, {%0,%1,%2,%3};"
        : "+f"(c[0]), "+f"(c[1]), "+f"(c[2]), "+f"(c[3])
        : "r"(a[0]), "r"(a[1]), "r"(a[2]), "r"(a[3]), "r"(b[0]), "r"(b[1]));
}
__device__ __forceinline__ void cpa16(u32 dst, const void* src) {
    asm volatile("cp.async.cg.shared.global [%0], [%1], 16;" :: "r"(dst), "l"(src));
}
__device__ __forceinline__ void cpa_commit() {
    asm volatile("cp.async.commit_group;" ::: "memory");
}
__device__ __forceinline__ void cpa_wait1() {
    asm volatile("cp.async.wait_group 1;" ::: "memory");
}
__device__ __forceinline__ void cpa_wait0() {
    asm volatile("cp.async.wait_group 0;" ::: "memory");
}

__device__ __forceinline__ void split2(float v, __nv_bfloat16& h, __nv_bfloat16& l) {
    h = __float2bfloat16_rn(v);
    l = __float2bfloat16_rn(v - __bfloat162float(h));
}

__global__ void __launch_bounds__(NTHR, 1)
rnn_kernel(const float* __restrict__ x,   const float* __restrict__ Wa,
           const float* __restrict__ ba,  const float* __restrict__ Wb,
           const float* __restrict__ bbv, const float* __restrict__ gamma,
           const float* __restrict__ beta, float* __restrict__ out)
{
    extern __shared__ __nv_bfloat16 smb[];
    __nv_bfloat16* sWaHi = smb + OFF_WAHI;
    __nv_bfloat16* sWaLo = smb + OFF_WALO;
    __nv_bfloat16* sWbHi = smb + OFF_WBHI;
    __nv_bfloat16* sWbLo = smb + OFF_WBLO;
    float* sRed = (float*)(smb + OFF_BUF);   // aliases buffers (safe: used only in epilogues)

    const int tid = threadIdx.x;
    const int cta = blockIdx.x;
    const int lane = tid & 31, wid = tid >> 5;

    // ---- one-time: weights -> smem bf16 hi/lo planes ----
    for (int idx = tid; idx < 16*C2; idx += NTHR) {
        int r = idx >> 11, k = idx & (C2-1);
        float v = Wa[(size_t)(cta*16 + r)*C2 + k];
        split2(v, sWaHi[r*WS + k], sWaLo[r*WS + k]);
    }
    for (int idx = tid; idx < 8*C2; idx += NTHR) {
        int r = idx >> 11, k = idx & (C2-1);
        float v = Wb[(size_t)(cta*8 + r)*C2 + k];
        split2(v, sWbHi[r*WS + k], sWbLo[r*WS + k]);
    }
    // ---- one-time: x -> bf16 hi/lo global planes ----
    {
        int g = cta*NTHR + tid;
        const float4* x4 = (const float4*)x;
        uint2* xh = (uint2*)g_x_hi;
        uint2* xl = (uint2*)g_x_lo;
        for (int i = 0; i < 128; ++i) {
            int idx = g + (i << 16);
            float4 v = x4[idx];
            __nv_bfloat16 h0,h1,h2,h3,l0,l1,l2,l3;
            split2(v.x,h0,l0); split2(v.y,h1,l1); split2(v.z,h2,l2); split2(v.w,h3,l3);
            __nv_bfloat162 ph0 = {h0,h1}, ph1 = {h2,h3}, pl0 = {l0,l1}, pl1 = {l2,l3};
            uint2 uh, ul;
            uh.x = *(u32*)&ph0; uh.y = *(u32*)&ph1;
            ul.x = *(u32*)&pl0; ul.y = *(u32*)&pl1;
            xh[idx] = uh; xl[idx] = ul;
        }
    }
    {
        int idx = cta*NTHR + tid;
        if (idx < BB*CC) {
            g_h_hi[idx] = __float2bfloat16_rn(0.f);
            g_h_lo[idx] = __float2bfloat16_rn(0.f);
        }
    }
    gbar();

    // ---- warp roles ----
    const int kspA = wid & 3, nt = wid >> 2;   // A: 4-way k-split, 4 n-tiles of 8 b
    const int mtB = wid & 1, kspB = wid >> 1;  // B: 8-way k-split, 2 m-tiles of 16 b
    const int myB = cta >> 2, myQ = cta & 3;

    const u32 smemBase = (u32)__cvta_generic_to_shared(smb);
    const int aRow = lane & 15, aKh = (lane >> 4) * 8;
    const int bRow = lane & 7,  bKh = ((lane >> 3) & 1) * 8;
    // weight frag bases (add kb*2 per kstep)
    const u32 waHi = smemBase + OFF_WAHI*2 + (aRow*WS + aKh)*2;
    const u32 waLo = smemBase + OFF_WALO*2 + (aRow*WS + aKh)*2;
    const u32 wbHi = smemBase + OFF_WBHI*2 + (bRow*WS + bKh)*2;
    const u32 wbLo = smemBase + OFF_WBLO*2 + (bRow*WS + bKh)*2;
    // act buffer frag bases per parity (add kl*2 per kstep)
    u32 acHiA[2], acLoA[2], acHiB[2], acLoB[2];
    #pragma unroll
    for (int p = 0; p < 2; ++p) {
        u32 bufHi = smemBase + (OFF_BUF + p*2*PLANE)*2;
        u32 bufLo = bufHi + PLANE*2;
        acHiA[p] = bufHi + ((nt*8 + bRow)*AS + bKh)*2;
        acLoA[p] = bufLo + ((nt*8 + bRow)*AS + bKh)*2;
        acHiB[p] = bufHi + ((mtB*16 + aRow)*AS + aKh)*2;
        acLoB[p] = bufLo + ((mtB*16 + aRow)*AS + aKh)*2;
    }

    // staging: thread -> (row = tid>>4, 8 elems at (tid&15)*8); 16B per plane
    const int srow = tid >> 4, skk = (tid & 15) << 3;
    u32 stDst[2];   // byte addr of hi-plane dest per parity; lo = +PLANE*2
    #pragma unroll
    for (int p = 0; p < 2; ++p)
        stDst[p] = smemBase + (OFF_BUF + p*2*PLANE + srow*AS + skk)*2;

    for (int t = 0; t < TT; ++t) {
        // ================= Phase A: y = gelu([h,x_t] @ Wa^T + ba) =================
        float c0[4] = {0,0,0,0}, c1[4] = {0,0,0,0}, c2[4] = {0,0,0,0};
        {
            // stage chunk ch into buf[ch&1]
            auto stageA = [&](int ch) {
                u32 d = stDst[ch & 1];
                if (ch < 8) {
                    size_t o = (size_t)srow*CC + ch*128 + skk;
                    cpa16(d, g_h_hi + o);
                    cpa16(d + PLANE*2, g_h_lo + o);
                } else {
                    size_t o = (size_t)srow*TT*CC + (size_t)t*CC + (ch - 8)*128 + skk;
                    cpa16(d, g_x_hi + o);
                    cpa16(d + PLANE*2, g_x_lo + o);
                }
                cpa_commit();
            };
            stageA(0);
            stageA(1);
            for (int ch = 0; ch < 16; ++ch) {
                if (ch < 15) cpa_wait1(); else cpa_wait0();
                __syncthreads();
                const int par = ch & 1;
                #pragma unroll
                for (int u = 0; u < 2; ++u) {
                    const int l = 2*kspA + u;
                    const int kb = ch*128 + 16*l;   // weights k
                    const int kl = 16*l;            // buffer k
                    u32 Ah[4], Al[4], Bh[2], Bl[2];
                    ldsm4(Ah, waHi + kb*2);
                    ldsm4(Al, waLo + kb*2);
                    ldsm2(Bh, acHiA[par] + kl*2);
                    ldsm2(Bl, acLoA[par] + kl*2);
                    mma16816(c0, Ah, Bh);
                    mma16816(c1, Ah, Bl);
                    mma16816(c2, Al, Bh);
                }
                __syncthreads();
                if (ch + 2 < 16) stageA(ch + 2);
            }
        }
        {   // partials -> sRed[kspA][16j][32b] (row stride 34)
            const int r0 = lane >> 2, cb = nt*8 + 2*(lane & 3);
            float2 v0 = make_float2(c0[0]+c1[0]+c2[0], c0[1]+c1[1]+c2[1]);
            float2 v1 = make_float2(c0[2]+c1[2]+c2[2], c0[3]+c1[3]+c2[3]);
            *(float2*)(sRed + (kspA*16 + r0    )*34 + cb) = v0;
            *(float2*)(sRed + (kspA*16 + r0 + 8)*34 + cb) = v1;
            __syncthreads();
            const int b = tid >> 4, j = tid & 15;
            float v = sRed[j*34 + b] + sRed[(16 + j)*34 + b]
                    + sRed[(32 + j)*34 + b] + sRed[(48 + j)*34 + b];
            const int jg = cta*16 + j;
            float y = geluf(v + __ldg(ba + jg));
            __nv_bfloat16 hh, ll;
            split2(y, hh, ll);
            g_y_hi[(size_t)b*C2 + jg] = hh;
            g_y_lo[(size_t)b*C2 + jg] = ll;
        }
        gbar();

        // ================= Phase B: y2 = y @ Wb^T + bb =================
        float d0[4] = {0,0,0,0}, d1[4] = {0,0,0,0}, d2[4] = {0,0,0,0};
        {
            auto stageB = [&](int ch) {
                u32 d = stDst[ch & 1];
                size_t o = (size_t)srow*C2 + ch*128 + skk;
                cpa16(d, g_y_hi + o);
                cpa16(d + PLANE*2, g_y_lo + o);
                cpa_commit();
            };
            stageB(0);
            stageB(1);
            for (int ch = 0; ch < 16; ++ch) {
                if (ch < 15) cpa_wait1(); else cpa_wait0();
                __syncthreads();
                const int par = ch & 1;
                {
                    const int kb = ch*128 + 16*kspB;
                    const int kl = 16*kspB;
                    u32 Ah[4], Al[4], Bh[2], Bl[2];
                    ldsm4(Ah, acHiB[par] + kl*2);
                    ldsm4(Al, acLoB[par] + kl*2);
                    ldsm2(Bh, wbHi + kb*2);
                    ldsm2(Bl, wbLo + kb*2);
                    mma16816(d0, Ah, Bh);
                    mma16816(d1, Ah, Bl);
                    mma16816(d2, Al, Bh);
                }
                __syncthreads();
                if (ch + 2 < 16) stageB(ch + 2);
            }
        }
        {   // partials -> sRed[kspB][32b][8j] (row stride 10)
            const int r0 = mtB*16 + (lane >> 2), cb = 2*(lane & 3);
            float2 v0 = make_float2(d0[0]+d1[0]+d2[0], d0[1]+d1[1]+d2[1]);
            float2 v1 = make_float2(d0[2]+d1[2]+d2[2], d0[3]+d1[3]+d2[3]);
            *(float2*)(sRed + (kspB*32 + r0    )*10 + cb) = v0;
            *(float2*)(sRed + (kspB*32 + r0 + 8)*10 + cb) = v1;
            __syncthreads();
            if (tid < 256) {
                const int b = tid >> 3, j = tid & 7;
                float v = 0.f;
                #pragma unroll
                for (int p = 0; p < 8; ++p) v += sRed[(p*32 + b)*10 + j];
                const int jg = cta*8 + j;
                v += __ldg(bbv + jg);
                __stcg(&g_y2[(size_t)b*CC + jg], v);
            }
        }
        gbar();

        // ================= Phase C: h = LN(y2)+y2 =================
        {
            float s = 0.f, sq = 0.f;
            #pragma unroll
            for (int i = tid; i < CC; i += NTHR) {
                float v = __ldcg(g_y2 + (size_t)myB*CC + i);
                s += v; sq += v*v;
            }
            #pragma unroll
            for (int o = 16; o; o >>= 1) {
                s  += __shfl_xor_sync(0xffffffffu, s,  o);
                sq += __shfl_xor_sync(0xffffffffu, sq, o);
            }
            if (lane == 0) { sRed[wid] = s; sRed[16 + wid] = sq; }
            __syncthreads();
            if (tid < 256) {
                float S = 0.f, Q = 0.f;
                #pragma unroll
                for (int w = 0; w < 16; ++w) { S += sRed[w]; Q += sRed[16 + w]; }
                float mu  = S * (1.0f / CC);
                float var = Q * (1.0f / CC) - mu * mu;
                float r   = rsqrtf(var + 1e-5f);
                int col = myQ * 256 + tid;
                float v  = __ldcg(g_y2 + (size_t)myB*CC + col);
                float hn = (v - mu) * r * __ldg(gamma + col) + __ldg(beta + col) + v;
                out[(size_t)myB*TT*CC + (size_t)t*CC + col] = hn;
                __nv_bfloat16 hh, ll;
                split2(hn, hh, ll);
                g_h_hi[(size_t)myB*CC + col] = hh;
                g_h_lo[(size_t)myB*CC + col] = ll;
            }
        }
        gbar();
    }
}

extern "C" void kernel_launch(void* const* d_in, const int* in_sizes, int n_in,
                              void* d_out, int out_size) {
    const float* x     = (const float*)d_in[0];
    const float* Wa    = (const float*)d_in[1];
    const float* ba    = (const float*)d_in[2];
    const float* Wb    = (const float*)d_in[3];
    const float* bbv   = (const float*)d_in[4];
    const float* gamma = (const float*)d_in[5];
    const float* beta  = (const float*)d_in[6];
    float* out = (float*)d_out;

    cudaFuncSetAttribute(rnn_kernel, cudaFuncAttributeMaxDynamicSharedMemorySize, SMEM_BYTES);
    rnn_kernel<<<NBLK, NTHR, SMEM_BYTES>>>(x, Wa, ba, Wb, bbv, gamma, beta, out);
}

// round 14
// speedup vs baseline: 1.8919x; 1.1179x over previous
#include <cuda_runtime.h>
#include <cuda_bf16.h>
#include <math.h>
#include <stdint.h>

typedef uint32_t u32;

#define NBLK 128
#define NTHR 512
#define BB   32
#define CC   1024
#define C2   2048
#define TT   1024
#define WS   2056   // weight row stride (bf16 elems): conflict-free LDSM

// SMEM byte layout: weights | 2x16KB act buffers | mbarriers
#define OFF_BUF_BYTES (48*WS*2)              // 197376 (128B aligned)
#define BUFSZ 16384
#define OFF_MBAR (OFF_BUF_BYTES + 2*BUFSZ)   // 230144
#define SMEM_BYTES (OFF_MBAR + 64)           // 230208

// GMEM staging (chunk-major, swizzled, [hi 8KB | lo 8KB] per 16KB chunk)
__device__ __align__(128) unsigned char g_xs[134217728]; // [t][8 chunks][16KB]
__device__ __align__(128) unsigned char g_hs[131072];    // [8 chunks][16KB]
__device__ __align__(128) unsigned char g_ys[262144];    // [16 chunks][16KB]
__device__ float g_y2[BB*CC];
__device__ unsigned g_cnt;
__device__ volatile unsigned g_gen;

__device__ __forceinline__ float geluf(float u) {
    return 0.5f * u * (1.0f + erff(u * 0.70710678118654752440f));
}

__device__ __forceinline__ void gbar() {
    __syncthreads();
    if (threadIdx.x == 0) {
        __threadfence();
        unsigned gen = g_gen;
        if (atomicAdd(&g_cnt, 1u) == NBLK - 1) {
            atomicExch(&g_cnt, 0u);
            __threadfence();
            g_gen = gen + 1u;
        } else {
            while (g_gen == gen) {}
        }
        __threadfence();
    }
    __syncthreads();
}

__device__ __forceinline__ void ldsm4(u32 (&r)[4], u32 addr) {
    asm volatile("ldmatrix.sync.aligned.m8n8.x4.shared.b16 {%0,%1,%2,%3}, [%4];"
        : "=r"(r[0]), "=r"(r[1]), "=r"(r[2]), "=r"(r[3]) : "r"(addr));
}
__device__ __forceinline__ void ldsm2(u32 (&r)[2], u32 addr) {
    asm volatile("ldmatrix.sync.aligned.m8n8.x2.shared.b16 {%0,%1}, [%2];"
        : "=r"(r[0]), "=r"(r[1]) : "r"(addr));
}
__device__ __forceinline__ void mma16816(float (&c)[4], const u32 (&a)[4], const u32 (&b)[2]) {
    asm volatile("mma.sync.aligned.m16n8k16.row.col.f32.bf16.bf16.f32 "
        "{%0,%1,%2,%3}, {%4,%5,%6,%7}, {%8,%9}, {%0,%1,%2,%3};"
        : "+f"(c[0]), "+f"(c[1]), "+f"(c[2]), "+f"(c[3])
        : "r"(a[0]), "r"(a[1]), "r"(a[2]), "r"(a[3]), "r"(b[0]), "r"(b[1]));
}

__device__ __forceinline__ void mbar_init(u32 a, u32 cnt) {
    asm volatile("mbarrier.init.shared.b64 [%0], %1;" :: "r"(a), "r"(cnt) : "memory");
}
__device__ __forceinline__ void mbar_arrive(u32 a) {
    asm volatile("mbarrier.arrive.shared.b64 _, [%0];" :: "r"(a) : "memory");
}
__device__ __forceinline__ void mbar_expect_tx(u32 a, u32 n) {
    asm volatile("mbarrier.arrive.expect_tx.shared.b64 _, [%0], %1;" :: "r"(a), "r"(n) : "memory");
}
__device__ __forceinline__ void mbar_wait(u32 a, u32 ph) {
    u32 done;
    asm volatile("{\n\t.reg .pred p;\n\t"
        "mbarrier.try_wait.parity.acquire.cta.shared::cta.b64 p, [%1], %2;\n\t"
        "selp.b32 %0, 1, 0, p;\n\t}"
        : "=r"(done) : "r"(a), "r"(ph) : "memory");
    if (!done) {
        asm volatile("{\n\t.reg .pred P1;\n\t"
            "WAIT_LOOP_%=:\n\t"
            "mbarrier.try_wait.parity.acquire.cta.shared::cta.b64 P1, [%0], %1, 0x989680;\n\t"
            "@P1 bra.uni WAIT_DONE_%=;\n\t"
            "bra.uni WAIT_LOOP_%=;\n\t"
            "WAIT_DONE_%=:\n\t}"
            :: "r"(a), "r"(ph) : "memory");
    }
}
__device__ __forceinline__ void bulk_cp(u32 dst, const void* src, u32 bytes, u32 mbar) {
    asm volatile("cp.async.bulk.shared::cluster.global.mbarrier::complete_tx::bytes "
        "[%0], [%1], %2, [%3];" :: "r"(dst), "l"(src), "r"(bytes), "r"(mbar) : "memory");
}
__device__ __forceinline__ void fence_async() {
    asm volatile("fence.proxy.async.shared::cta;" ::: "memory");
}

__device__ __forceinline__ void split2(float v, __nv_bfloat16& h, __nv_bfloat16& l) {
    h = __float2bfloat16_rn(v);
    l = __float2bfloat16_rn(v - __bfloat162float(h));
}
__device__ __forceinline__ u32 packhl(__nv_bfloat16 a, __nv_bfloat16 b) {
    __nv_bfloat162 p = {a, b};
    return *(u32*)&p;
}

// swizzled byte offset within an 8KB plane (32 rows x 128 bf16 cols)
// blocked atoms: 8 rows x 64 cols (128B rows), SW128
__device__ __forceinline__ u32 swz(u32 r, u32 c) {
    u32 b = (((r >> 3) + ((c >> 6) << 2)) << 10) + ((r & 7) << 7) + ((c & 63) << 1);
    return b ^ ((b >> 3) & 0x70);
}

__global__ void __launch_bounds__(NTHR, 1)
rnn_kernel(const float* __restrict__ x,   const float* __restrict__ Wa,
           const float* __restrict__ ba,  const float* __restrict__ Wb,
           const float* __restrict__ bbv, const float* __restrict__ gamma,
           const float* __restrict__ beta, float* __restrict__ out)
{
    extern __shared__ unsigned char smb[];
    __nv_bfloat16* sWaHi = (__nv_bfloat16*)(smb);
    __nv_bfloat16* sWaLo = (__nv_bfloat16*)(smb + 16*WS*2);
    __nv_bfloat16* sWbHi = (__nv_bfloat16*)(smb + 32*WS*2);
    __nv_bfloat16* sWbLo = (__nv_bfloat16*)(smb + 40*WS*2);
    float* sRed = (float*)(smb + OFF_BUF_BYTES);   // aliases buffers; epilogue-only

    const int tid = threadIdx.x;
    const int cta = blockIdx.x;
    const int lane = tid & 31, wid = tid >> 5;

    const u32 smemBase = (u32)__cvta_generic_to_shared(smb);
    const u32 mbFull[2]  = {smemBase + OFF_MBAR,      smemBase + OFF_MBAR + 8};
    const u32 mbEmpty[2] = {smemBase + OFF_MBAR + 16, smemBase + OFF_MBAR + 24};
    const u32 bufB[2]    = {smemBase + OFF_BUF_BYTES, smemBase + OFF_BUF_BYTES + BUFSZ};

    if (tid == 0) {
        mbar_init(mbFull[0], 1);  mbar_init(mbFull[1], 1);
        mbar_init(mbEmpty[0], 16); mbar_init(mbEmpty[1], 16);
    }

    // ---- one-time: weights -> smem bf16 hi/lo planes ----
    for (int idx = tid; idx < 16*C2; idx += NTHR) {
        int r = idx >> 11, k = idx & (C2-1);
        float v = Wa[(size_t)(cta*16 + r)*C2 + k];
        split2(v, sWaHi[r*WS + k], sWaLo[r*WS + k]);
    }
    for (int idx = tid; idx < 8*C2; idx += NTHR) {
        int r = idx >> 11, k = idx & (C2-1);
        float v = Wb[(size_t)(cta*8 + r)*C2 + k];
        split2(v, sWbHi[r*WS + k], sWbLo[r*WS + k]);
    }
    // ---- one-time: x -> chunk-major swizzled hi/lo (this CTA owns 8 t values) ----
    for (int tt = cta*8; tt < cta*8 + 8; ++tt) {
        for (int p = tid; p < 32*512; p += NTHR) {      // 16384 col-pairs per t
            int b = p >> 9, c0 = (p & 511) << 1;
            float2 v = *(const float2*)(x + ((size_t)b*TT + tt)*CC + c0);
            __nv_bfloat16 h0,l0,h1,l1;
            split2(v.x, h0, l0);
            split2(v.y, h1, l1);
            unsigned char* base = g_xs + ((size_t)tt*8 + (c0 >> 7))*BUFSZ;
            u32 off = swz((u32)b, (u32)(c0 & 127));
            *(u32*)(base + off)        = packhl(h0, h1);
            *(u32*)(base + 8192 + off) = packhl(l0, l1);
        }
    }
    // ---- h0 = 0 ----
    {
        int g = cta*NTHR + tid;
        if (g < 32768) ((u32*)g_hs)[g] = 0u;
    }
    gbar();

    // ---- warp roles ----
    const int kspA = wid & 3, nt = wid >> 2;   // A: 4 n-tiles(8b) x 4-way k-split
    const int mtB = wid & 1, kspB = wid >> 1;  // B: 2 m-tiles(16b) x 8-way k-split
    const int myB = cta >> 2, myQ = cta & 3;

    // weight frag bases (bytes; add kb*2 per kstep)
    const int aRow = lane & 15, aKh = (lane >> 4) * 8;
    const int bRow = lane & 7,  bKh = ((lane >> 3) & 1) * 8;
    const u32 waHi = smemBase + 0        + (aRow*WS + aKh)*2;
    const u32 waLo = smemBase + 16*WS*2  + (aRow*WS + aKh)*2;
    const u32 wbHi = smemBase + 32*WS*2  + (bRow*WS + bKh)*2;
    const u32 wbLo = smemBase + 40*WS*2  + (bRow*WS + bKh)*2;

    // act frag addresses in swizzled buffers (hi plane; lo = +8192)
    u32 aAct[2][2], bAct[2];
    #pragma unroll
    for (int s = 0; s < 2; ++s) {
        #pragma unroll
        for (int u = 0; u < 2; ++u)
            aAct[s][u] = bufB[s] + swz((u32)(nt*8 + (lane & 7)),
                                       (u32)(32*kspA + 16*u + ((lane >> 3) & 1)*8));
        bAct[s] = bufB[s] + swz((u32)(mtB*16 + (lane & 15)),
                                (u32)(16*kspB + ((lane >> 4) & 1)*8));
    }

    // pipeline state
    int cPh[2] = {0, 0};             // consumer full-parity (all threads)
    int pPh[2] = {0, 0};             // producer empty-parity (tid0)
    int pFirst[2] = {1, 1};          // skip empty-wait on first-ever use

    for (int t = 0; t < TT; ++t) {
        // ================= Phase A: y = gelu([h,x_t] @ Wa^T + ba) =================
        float c0a[4] = {0,0,0,0}, c1a[4] = {0,0,0,0}, c2a[4] = {0,0,0,0};
        {
            auto stageA = [&](int ch) {
                int s = ch & 1;
                if (pFirst[s]) pFirst[s] = 0;
                else { mbar_wait(mbEmpty[s], pPh[s]); pPh[s] ^= 1; }
                const void* src = (ch < 8)
                    ? (const void*)(g_hs + (size_t)ch*BUFSZ)
                    : (const void*)(g_xs + ((size_t)t*8 + (ch - 8))*BUFSZ);
                mbar_expect_tx(mbFull[s], BUFSZ);
                bulk_cp(bufB[s], src, BUFSZ, mbFull[s]);
            };
            if (tid == 0) { fence_async(); stageA(0); stageA(1); }
            #pragma unroll 2
            for (int ch = 0; ch < 16; ++ch) {
                const int s = ch & 1;
                mbar_wait(mbFull[s], cPh[s]); cPh[s] ^= 1;
                #pragma unroll
                for (int u = 0; u < 2; ++u) {
                    const int kb = ch*128 + 32*kspA + 16*u;
                    u32 Ah[4], Al[4], Bh[2], Bl[2];
                    ldsm4(Ah, waHi + kb*2);
                    ldsm4(Al, waLo + kb*2);
                    ldsm2(Bh, aAct[s][u]);
                    ldsm2(Bl, aAct[s][u] + 8192);
                    mma16816(c0a, Ah, Bh);
                    mma16816(c1a, Ah, Bl);
                    mma16816(c2a, Al, Bh);
                }
                __syncwarp();
                if (lane == 0) mbar_arrive(mbEmpty[s]);
                if (tid == 0 && ch < 14) stageA(ch + 2);
            }
        }
        {   // partials -> sRed[kspA][16j][32b] (row stride 34)
            const int r0 = lane >> 2, cb = nt*8 + 2*(lane & 3);
            *(float2*)(sRed + (kspA*16 + r0    )*34 + cb) = make_float2(c0a[0]+c1a[0]+c2a[0], c0a[1]+c1a[1]+c2a[1]);
            *(float2*)(sRed + (kspA*16 + r0 + 8)*34 + cb) = make_float2(c0a[2]+c1a[2]+c2a[2], c0a[3]+c1a[3]+c2a[3]);
            __syncthreads();
            if (tid < 256) {
                const int b = tid >> 3, j2 = (tid & 7)*2;
                const int jg0 = cta*16 + j2;
                float v0 = sRed[j2*34 + b] + sRed[(16 + j2)*34 + b]
                         + sRed[(32 + j2)*34 + b] + sRed[(48 + j2)*34 + b];
                float v1 = sRed[(j2+1)*34 + b] + sRed[(16 + j2+1)*34 + b]
                         + sRed[(32 + j2+1)*34 + b] + sRed[(48 + j2+1)*34 + b];
                float y0 = geluf(v0 + __ldg(ba + jg0));
                float y1 = geluf(v1 + __ldg(ba + jg0 + 1));
                __nv_bfloat16 h0,l0,h1,l1;
                split2(y0, h0, l0);
                split2(y1, h1, l1);
                unsigned char* base = g_ys + (size_t)(jg0 >> 7)*BUFSZ;
                u32 off = swz((u32)b, (u32)(jg0 & 127));
                *(u32*)(base + off)        = packhl(h0, h1);
                *(u32*)(base + 8192 + off) = packhl(l0, l1);
            }
        }
        gbar();

        // ================= Phase B: y2 = y @ Wb^T + bb =================
        float d0[4] = {0,0,0,0}, d1[4] = {0,0,0,0}, d2[4] = {0,0,0,0};
        {
            auto stageB = [&](int ch) {
                int s = ch & 1;
                mbar_wait(mbEmpty[s], pPh[s]); pPh[s] ^= 1;
                mbar_expect_tx(mbFull[s], BUFSZ);
                bulk_cp(bufB[s], g_ys + (size_t)ch*BUFSZ, BUFSZ, mbFull[s]);
            };
            if (tid == 0) { fence_async(); stageB(0); stageB(1); }
            #pragma unroll 2
            for (int ch = 0; ch < 16; ++ch) {
                const int s = ch & 1;
                mbar_wait(mbFull[s], cPh[s]); cPh[s] ^= 1;
                {
                    const int kb = ch*128 + 16*kspB;
                    u32 Ah[4], Al[4], Bh[2], Bl[2];
                    ldsm4(Ah, bAct[s]);
                    ldsm4(Al, bAct[s] + 8192);
                    ldsm2(Bh, wbHi + kb*2);
                    ldsm2(Bl, wbLo + kb*2);
                    mma16816(d0, Ah, Bh);
                    mma16816(d1, Ah, Bl);
                    mma16816(d2, Al, Bh);
                }
                __syncwarp();
                if (lane == 0) mbar_arrive(mbEmpty[s]);
                if (tid == 0 && ch < 14) stageB(ch + 2);
            }
        }
        {   // partials -> sRed[kspB][32b][8j] (row stride 10)
            const int r0 = mtB*16 + (lane >> 2), cb = 2*(lane & 3);
            *(float2*)(sRed + (kspB*32 + r0    )*10 + cb) = make_float2(d0[0]+d1[0]+d2[0], d0[1]+d1[1]+d2[1]);
            *(float2*)(sRed + (kspB*32 + r0 + 8)*10 + cb) = make_float2(d0[2]+d1[2]+d2[2], d0[3]+d1[3]+d2[3]);
            __syncthreads();
            if (tid < 256) {
                const int b = tid >> 3, j = tid & 7;
                float v = 0.f;
                #pragma unroll
                for (int p = 0; p < 8; ++p) v += sRed[(p*32 + b)*10 + j];
                const int jg = cta*8 + j;
                v += __ldg(bbv + jg);
                __stcg(&g_y2[(size_t)b*CC + jg], v);
            }
        }
        gbar();

        // ================= Phase C: h = LN(y2)+y2 =================
        {
            float s = 0.f, sq = 0.f;
            #pragma unroll
            for (int i = tid; i < CC; i += NTHR) {
                float v = __ldcg(g_y2 + (size_t)myB*CC + i);
                s += v; sq += v*v;
            }
            #pragma unroll
            for (int o = 16; o; o >>= 1) {
                s  += __shfl_xor_sync(0xffffffffu, s,  o);
                sq += __shfl_xor_sync(0xffffffffu, sq, o);
            }
            if (lane == 0) { sRed[wid] = s; sRed[16 + wid] = sq; }
            __syncthreads();
            if (tid < 128) {
                float S = 0.f, Q = 0.f;
                #pragma unroll
                for (int w = 0; w < 16; ++w) { S += sRed[w]; Q += sRed[16 + w]; }
                float mu  = S * (1.0f / CC);
                float var = Q * (1.0f / CC) - mu * mu;
                float r   = rsqrtf(var + 1e-5f);
                int c0 = myQ * 256 + tid*2;
                float v0 = __ldcg(g_y2 + (size_t)myB*CC + c0);
                float v1 = __ldcg(g_y2 + (size_t)myB*CC + c0 + 1);
                float hn0 = (v0 - mu) * r * __ldg(gamma + c0)     + __ldg(beta + c0)     + v0;
                float hn1 = (v1 - mu) * r * __ldg(gamma + c0 + 1) + __ldg(beta + c0 + 1) + v1;
                *(float2*)(out + (size_t)myB*TT*CC + (size_t)t*CC + c0) = make_float2(hn0, hn1);
                __nv_bfloat16 h0,l0,h1,l1;
                split2(hn0, h0, l0);
                split2(hn1, h1, l1);
                unsigned char* base = g_hs + (size_t)(c0 >> 7)*BUFSZ;
                u32 off = swz((u32)myB, (u32)(c0 & 127));
                *(u32*)(base + off)        = packhl(h0, h1);
                *(u32*)(base + 8192 + off) = packhl(l0, l1);
            }
        }
        gbar();
    }
}

extern "C" void kernel_launch(void* const* d_in, const int* in_sizes, int n_in,
                              void* d_out, int out_size) {
    const float* x     = (const float*)d_in[0];
    const float* Wa    = (const float*)d_in[1];
    const float* ba    = (const float*)d_in[2];
    const float* Wb    = (const float*)d_in[3];
    const float* bbv   = (const float*)d_in[4];
    const float* gamma = (const float*)d_in[5];
    const float* beta  = (const float*)d_in[6];
    float* out = (float*)d_out;

    cudaFuncSetAttribute(rnn_kernel, cudaFuncAttributeMaxDynamicSharedMemorySize, SMEM_BYTES);
    rnn_kernel<<<NBLK, NTHR, SMEM_BYTES>>>(x, Wa, ba, Wb, bbv, gamma, beta, out);
}